// round 8
// baseline (speedup 1.0000x reference)
#include <cuda_runtime.h>
#include <cuda_bf16.h>
#include <cstdint>

#define N_MAX   4096
#define D_MAX   2048
#define MARGIN  0.3f
#define NPART   16

__device__ float           g_sq[N_MAX];
__device__ unsigned        g_max2[N_MAX];  // max clamped dist^2, same-class (uint-encoded fp32 >= 0)
__device__ unsigned        g_min2[N_MAX];  // min clamped dist^2, zero_neg   (uint-encoded fp32 >= 0)
__device__ int             g_flag;
__device__ int             g_done;
__device__ float           g_partial[NPART];
__device__ __nv_bfloat16   g_xb[(size_t)N_MAX * D_MAX];   // bf16 copy of inputs (16 MB)

// ======================= prep: norms (fp32 exact) + bf16 convert + flag =====
__global__ void prep_kernel(const float* __restrict__ x, const int* __restrict__ tgt,
                            int n, int d) {
    int warp = (blockIdx.x * blockDim.x + threadIdx.x) >> 5;
    int lane = threadIdx.x & 31;

    if (warp < n) {
        const float4* row = (const float4*)(x + (size_t)warp * d);
        uint4* orow = (uint4*)(g_xb + (size_t)warp * d);
        int nv = d >> 3;
        float s = 0.f;
        for (int v = lane; v < nv; v += 32) {
            float4 f0 = row[v * 2];
            float4 f1 = row[v * 2 + 1];
            s += f0.x * f0.x + f0.y * f0.y + f0.z * f0.z + f0.w * f0.w;
            s += f1.x * f1.x + f1.y * f1.y + f1.z * f1.z + f1.w * f1.w;
            __nv_bfloat162 h0 = __floats2bfloat162_rn(f0.x, f0.y);
            __nv_bfloat162 h1 = __floats2bfloat162_rn(f0.z, f0.w);
            __nv_bfloat162 h2 = __floats2bfloat162_rn(f1.x, f1.y);
            __nv_bfloat162 h3 = __floats2bfloat162_rn(f1.z, f1.w);
            uint4 o;
            o.x = *(uint32_t*)&h0; o.y = *(uint32_t*)&h1;
            o.z = *(uint32_t*)&h2; o.w = *(uint32_t*)&h3;
            orow[v] = o;
        }
        #pragma unroll
        for (int o = 16; o; o >>= 1) s += __shfl_xor_sync(0xffffffffu, s, o);
        if (lane == 0) {
            g_sq[warp]   = s;
            g_max2[warp] = 0u;
            g_min2[warp] = 0x7f800000u;
        }
    }

    if (blockIdx.x == 0) {
        int t0 = tgt[0];
        int loc = 0;
        for (int j = threadIdx.x; j < n; j += blockDim.x) {
            int tj = tgt[j];
            if ((t0 != tj) && (t0 == 0 || tj == 0)) loc = 1;
        }
        int f = __syncthreads_or(loc);
        if (threadIdx.x == 0) { g_flag = f; g_done = 0; }
    }
}

// ======================= PTX helpers (baseline ISA only) ====================
__device__ __forceinline__ uint32_t smem_u32(const void* p) {
    uint32_t a;
    asm("{ .reg .u64 t; cvta.to.shared.u64 t, %1; cvt.u32.u64 %0, t; }" : "=r"(a) : "l"(p));
    return a;
}
#define CP16(sa, ga) \
    asm volatile("cp.async.cg.shared.global [%0], [%1], 16;" :: "r"(sa), "l"(ga) : "memory")
#define CP_COMMIT()  asm volatile("cp.async.commit_group;" ::: "memory")
#define CP_WAIT2()   asm volatile("cp.async.wait_group 2;" ::: "memory")

#define LDSM_X4(r, a) \
    asm volatile("ldmatrix.sync.aligned.m8n8.x4.shared.b16 {%0,%1,%2,%3}, [%4];" \
        : "=r"((r)[0]), "=r"((r)[1]), "=r"((r)[2]), "=r"((r)[3]) : "r"(a))
#define LDSM_X2(r, a) \
    asm volatile("ldmatrix.sync.aligned.m8n8.x2.shared.b16 {%0,%1}, [%2];" \
        : "=r"((r)[0]), "=r"((r)[1]) : "r"(a))

#define MMA16816(c, a, b) \
    asm volatile("mma.sync.aligned.m16n8k16.row.col.f32.bf16.bf16.f32 " \
        "{%0,%1,%2,%3},{%4,%5,%6,%7},{%8,%9},{%0,%1,%2,%3};" \
        : "+f"((c)[0]), "+f"((c)[1]), "+f"((c)[2]), "+f"((c)[3]) \
        : "r"((a)[0]), "r"((a)[1]), "r"((a)[2]), "r"((a)[3]), "r"((b)[0]), "r"((b)[1]))

// ======================= bf16 mma.sync fused GEMM + reduction + loss ========
// Block tile 128 (M, i) x 256 (N, j); 8 warps in 2x4 grid, warp tile 64x64.
#define BMI   128
#define BNJ   256
#define BK    32                 // bf16 per K stage (64 B rows)
#define SROW  80                 // smem row stride (bytes), conflict-free ldmatrix
#define STG_A (BMI * SROW)       // 10240
#define STG_B (BNJ * SROW)       // 20480
#define STG   (STG_A + STG_B)    // 30720 per stage
#define NSTG  4
#define SM_RED   (NSTG * STG)              // 122880
#define SM_TOTAL (SM_RED + 4096)           // 126976

__global__ void __launch_bounds__(256, 1)
gemm_mma_kernel(const int* __restrict__ tgt, float* __restrict__ out,
                int n, int d, int nbj) {
    extern __shared__ char smem[];
    const uint32_t smemu = smem_u32(smem);
    const int tid  = threadIdx.x;
    const int wid  = tid >> 5;
    const int lane = tid & 31;

    // tile map: for each bj (256-wide), bi in [0, 2*bj+2) (128-tall).
    // cum(bj) = bj^2 + bj
    int p = blockIdx.x;
    int bj = 0;
    while (p >= (bj + 1) * (bj + 1) + (bj + 1)) bj++;
    int bi = p - (bj * bj + bj);
    const int iBase = bi * BMI;
    const int jBase = bj * BNJ;

    const __nv_bfloat16* xb = g_xb;
    const int nkt = d / BK;

    // warp tiling: 2 (M) x 4 (N), warp tile 64x64
    const int mWarp = (wid >> 2) * 64;
    const int nWarp = (wid & 3) * 64;

    float acc[4][8][4];
    #pragma unroll
    for (int mt = 0; mt < 4; mt++)
        #pragma unroll
        for (int nt = 0; nt < 8; nt++)
            #pragma unroll
            for (int e = 0; e < 4; e++) acc[mt][nt][e] = 0.f;

    auto issue = [&](int s, int kt) {
        uint32_t aS = smemu + s * STG;
        uint32_t bS = aS + STG_A;
        // A: 128 rows * 4 chunks = 512; B: 256 rows * 4 chunks = 1024
        #pragma unroll
        for (int t = 0; t < 2; t++) {
            int chunk = tid + t * 256;
            int r = chunk >> 2, c = chunk & 3;
            const char* gA = (const char*)(xb + (size_t)(iBase + r) * d) + kt * 64 + c * 16;
            CP16(aS + r * SROW + c * 16, gA);
        }
        #pragma unroll
        for (int t = 0; t < 4; t++) {
            int chunk = tid + t * 256;
            int r = chunk >> 2, c = chunk & 3;
            const char* gB = (const char*)(xb + (size_t)(jBase + r) * d) + kt * 64 + c * 16;
            CP16(bS + r * SROW + c * 16, gB);
        }
    };

    issue(0, 0); CP_COMMIT();
    issue(1, 1); CP_COMMIT();
    issue(2, 2); CP_COMMIT();

    const uint32_t aRowOff = (mWarp + (lane & 15)) * SROW + ((lane >> 4) & 1) * 16;
    const uint32_t bRowOff = (nWarp + (lane & 7))  * SROW + ((lane >> 3) & 1) * 16;

    for (int kt = 0; kt < nkt; kt++) {
        CP_WAIT2();
        __syncthreads();
        if (kt + 3 < nkt) issue((kt + 3) % NSTG, kt + 3);
        CP_COMMIT();

        int s = kt % NSTG;
        uint32_t aS = smemu + s * STG;
        uint32_t bS = aS + STG_A;

        // register double-buffered fragments: load kk=0, then overlap kk=1 loads
        uint32_t ra[2][4][4], rb[2][8][2];
        #pragma unroll
        for (int mt = 0; mt < 4; mt++)
            LDSM_X4(ra[0][mt], aS + aRowOff + mt * 16 * SROW);
        #pragma unroll
        for (int nt = 0; nt < 8; nt++)
            LDSM_X2(rb[0][nt], bS + bRowOff + nt * 8 * SROW);

        #pragma unroll
        for (int kk = 0; kk < 2; kk++) {
            if (kk == 0) {
                #pragma unroll
                for (int mt = 0; mt < 4; mt++)
                    LDSM_X4(ra[1][mt], aS + aRowOff + mt * 16 * SROW + 32);
                #pragma unroll
                for (int nt = 0; nt < 8; nt++)
                    LDSM_X2(rb[1][nt], bS + bRowOff + nt * 8 * SROW + 32);
            }
            #pragma unroll
            for (int mt = 0; mt < 4; mt++)
                #pragma unroll
                for (int nt = 0; nt < 8; nt++)
                    MMA16816(acc[mt][nt], ra[kk][mt], rb[kk][nt]);
        }
    }
    __syncthreads();

    // --- epilogue: dist^2 + masked max/min reductions ------------------------
    // acc fragment (m16n8): e0:(r,c) e1:(r,c+1) e2:(r+8,c) e3:(r+8,c+1)
    float sqi[8], sqj[16];
    int   ti[8], tj[16];
    #pragma unroll
    for (int mt = 0; mt < 4; mt++)
        #pragma unroll
        for (int h = 0; h < 2; h++) {
            int gi = iBase + mWarp + mt * 16 + (lane >> 2) + h * 8;
            sqi[mt * 2 + h] = g_sq[gi];
            ti[mt * 2 + h]  = tgt[gi];
        }
    #pragma unroll
    for (int nt = 0; nt < 8; nt++)
        #pragma unroll
        for (int pp = 0; pp < 2; pp++) {
            int gj = jBase + nWarp + nt * 8 + 2 * (lane & 3) + pp;
            sqj[nt * 2 + pp] = g_sq[gj];
            tj[nt * 2 + pp]  = tgt[gj];
        }

    const unsigned UINF = 0x7f800000u;
    unsigned rmax[8], rmin[8], cmax[16], cmin[16];
    #pragma unroll
    for (int q = 0; q < 8; q++)  { rmax[q] = 0u; rmin[q] = UINF; }
    #pragma unroll
    for (int q = 0; q < 16; q++) { cmax[q] = 0u; cmin[q] = UINF; }

    #pragma unroll
    for (int mt = 0; mt < 4; mt++)
        #pragma unroll
        for (int nt = 0; nt < 8; nt++)
            #pragma unroll
            for (int e = 0; e < 4; e++) {
                int h = e >> 1, pp = e & 1;
                int ri = mt * 2 + h, cj = nt * 2 + pp;
                float d2 = fmaxf(sqi[ri] + sqj[cj] - 2.f * acc[mt][nt][(h << 1) | pp], 1e-12f);
                unsigned b = __float_as_uint(d2);
                bool same = (ti[ri] == tj[cj]);
                bool zn   = !same && (ti[ri] == 0 || tj[cj] == 0);
                if (same) { rmax[ri] = max(rmax[ri], b); cmax[cj] = max(cmax[cj], b); }
                if (zn)   { rmin[ri] = min(rmin[ri], b); cmin[cj] = min(cmin[cj], b); }
            }

    // shared reduction: 128 i-rows + 256 j-cols = 384 slots
    unsigned* sredmax = (unsigned*)(smem + SM_RED);
    unsigned* sredmin = sredmax + 384;
    sredmax[tid] = 0u;  sredmin[tid] = UINF;
    if (tid < 128) { sredmax[tid + 256] = 0u; sredmin[tid + 256] = UINF; }
    __syncthreads();

    #pragma unroll
    for (int mt = 0; mt < 4; mt++)
        #pragma unroll
        for (int h = 0; h < 2; h++) {
            int q = mt * 2 + h;
            int loc = mWarp + mt * 16 + (lane >> 2) + h * 8;
            if (rmax[q]) atomicMax(&sredmax[loc], rmax[q]);
            if (rmin[q] != UINF) atomicMin(&sredmin[loc], rmin[q]);
        }
    #pragma unroll
    for (int nt = 0; nt < 8; nt++)
        #pragma unroll
        for (int pp = 0; pp < 2; pp++) {
            int q = nt * 2 + pp;
            int loc = 128 + nWarp + nt * 8 + 2 * (lane & 3) + pp;
            if (cmax[q]) atomicMax(&sredmax[loc], cmax[q]);
            if (cmin[q] != UINF) atomicMin(&sredmin[loc], cmin[q]);
        }
    __syncthreads();

    {
        int row = (tid < 128) ? (iBase + tid) : (jBase + (tid - 128));
        if (sredmax[tid]) atomicMax(&g_max2[row], sredmax[tid]);
        if (sredmin[tid] != UINF) atomicMin(&g_min2[row], sredmin[tid]);
        if (tid < 128) {
            int row2 = jBase + tid + 128;
            if (sredmax[tid + 256]) atomicMax(&g_max2[row2], sredmax[tid + 256]);
            if (sredmin[tid + 256] != UINF) atomicMin(&g_min2[row2], sredmin[tid + 256]);
        }
    }

    // --- last-CTA tail: full loss reduction ----------------------------------
    __threadfence();
    __shared__ int amlast;
    if (tid == 0) amlast = (atomicAdd(&g_done, 1) == (int)gridDim.x - 1);
    __syncthreads();
    if (amlast) {
        int flag = g_flag;
        float s = 0.f;
        for (int i = tid; i < n; i += 256) {
            float ap = sqrtf(__uint_as_float(__ldcg(&g_max2[i])));
            float an = flag ? sqrtf(__uint_as_float(__ldcg(&g_min2[i]))) : 0.f;
            s += fmaxf(ap - an + MARGIN, 0.f);   // min2==+inf & flag -> -inf -> 0
        }
        float* ssum = (float*)(smem + SM_RED);
        ssum[tid] = s;
        __syncthreads();
        #pragma unroll
        for (int o = 128; o; o >>= 1) {
            if (tid < o) ssum[tid] += ssum[tid + o];
            __syncthreads();
        }
        if (tid == 0) out[0] = ssum[0] / (float)n;
    }
}

// ======================= legacy fp32 fallback (proven) ======================
#define LT    128
#define LKT   16
#define LPAD  4
__global__ void __launch_bounds__(256, 2)
gemm_reduce_legacy(const float* __restrict__ x, const int* __restrict__ tgt,
                   int n, int d, int nb) {
    int p = blockIdx.x, bi = 0, rem = p;
    while (rem >= nb - bi) { rem -= (nb - bi); bi++; }
    int bj = bi + rem;
    const int iBase = bi * LT;
    const int jBase = bj * LT;
    const int tid = threadIdx.x;
    const int tx = tid & 15;
    const int ty = tid >> 4;

    __shared__ float As[LKT][LT + LPAD];
    __shared__ float Bs[LKT][LT + LPAD];
    __shared__ unsigned sredmax[2 * LT];
    __shared__ unsigned sredmin[2 * LT];

    float acc[8][8];
    #pragma unroll
    for (int r = 0; r < 8; r++)
        #pragma unroll
        for (int c = 0; c < 8; c++) acc[r][c] = 0.f;

    const int nkt = d / LKT;
    float4 pa[2], pb[2];
    #pragma unroll
    for (int u = 0; u < 2; u++) {
        int idx = tid + u * 256, r = idx >> 2, c4 = idx & 3;
        pa[u] = *(const float4*)(x + (size_t)(iBase + r) * d + c4 * 4);
        pb[u] = *(const float4*)(x + (size_t)(jBase + r) * d + c4 * 4);
    }
    #pragma unroll
    for (int u = 0; u < 2; u++) {
        int idx = tid + u * 256, r = idx >> 2, c4 = idx & 3;
        As[c4*4+0][r]=pa[u].x; As[c4*4+1][r]=pa[u].y; As[c4*4+2][r]=pa[u].z; As[c4*4+3][r]=pa[u].w;
        Bs[c4*4+0][r]=pb[u].x; Bs[c4*4+1][r]=pb[u].y; Bs[c4*4+2][r]=pb[u].z; Bs[c4*4+3][r]=pb[u].w;
    }
    __syncthreads();
    for (int kt = 0; kt < nkt; kt++) {
        if (kt + 1 < nkt) {
            int k0 = (kt + 1) * LKT;
            #pragma unroll
            for (int u = 0; u < 2; u++) {
                int idx = tid + u * 256, r = idx >> 2, c4 = idx & 3;
                pa[u] = *(const float4*)(x + (size_t)(iBase + r) * d + k0 + c4 * 4);
                pb[u] = *(const float4*)(x + (size_t)(jBase + r) * d + k0 + c4 * 4);
            }
        }
        #pragma unroll
        for (int k = 0; k < LKT; k++) {
            float a[8], b[8];
            *(float4*)(a)   = *(const float4*)&As[k][ty*8];
            *(float4*)(a+4) = *(const float4*)&As[k][ty*8+4];
            *(float4*)(b)   = *(const float4*)&Bs[k][tx*8];
            *(float4*)(b+4) = *(const float4*)&Bs[k][tx*8+4];
            #pragma unroll
            for (int r = 0; r < 8; r++)
                #pragma unroll
                for (int c = 0; c < 8; c++) acc[r][c] += a[r] * b[c];
        }
        __syncthreads();
        if (kt + 1 < nkt) {
            #pragma unroll
            for (int u = 0; u < 2; u++) {
                int idx = tid + u * 256, r = idx >> 2, c4 = idx & 3;
                As[c4*4+0][r]=pa[u].x; As[c4*4+1][r]=pa[u].y; As[c4*4+2][r]=pa[u].z; As[c4*4+3][r]=pa[u].w;
                Bs[c4*4+0][r]=pb[u].x; Bs[c4*4+1][r]=pb[u].y; Bs[c4*4+2][r]=pb[u].z; Bs[c4*4+3][r]=pb[u].w;
            }
            __syncthreads();
        }
    }

    float sqi[8], sqj[8];
    int ti8[8], tj8[8];
    #pragma unroll
    for (int r = 0; r < 8; r++) { int i = iBase + ty*8 + r; sqi[r] = g_sq[i]; ti8[r] = tgt[i]; }
    #pragma unroll
    for (int c = 0; c < 8; c++) { int j = jBase + tx*8 + c; sqj[c] = g_sq[j]; tj8[c] = tgt[j]; }

    const float INF = __uint_as_float(0x7f800000u);
    float rmax[8], rmin[8], cmax[8], cmin[8];
    #pragma unroll
    for (int r = 0; r < 8; r++) { rmax[r] = 0.f; rmin[r] = INF; }
    #pragma unroll
    for (int c = 0; c < 8; c++) { cmax[c] = 0.f; cmin[c] = INF; }
    #pragma unroll
    for (int r = 0; r < 8; r++)
        #pragma unroll
        for (int c = 0; c < 8; c++) {
            float d2 = fmaxf(sqi[r] + sqj[c] - 2.f * acc[r][c], 1e-12f);
            bool same = (ti8[r] == tj8[c]);
            bool zn = !same && (ti8[r] == 0 || tj8[c] == 0);
            if (same) { rmax[r] = fmaxf(rmax[r], d2); cmax[c] = fmaxf(cmax[c], d2); }
            if (zn)   { rmin[r] = fminf(rmin[r], d2); cmin[c] = fminf(cmin[c], d2); }
        }
    sredmax[tid] = 0u; sredmin[tid] = 0x7f800000u;
    __syncthreads();
    #pragma unroll
    for (int r = 0; r < 8; r++) {
        atomicMax(&sredmax[ty*8+r], __float_as_uint(rmax[r]));
        atomicMin(&sredmin[ty*8+r], __float_as_uint(rmin[r]));
    }
    #pragma unroll
    for (int c = 0; c < 8; c++) {
        atomicMax(&sredmax[LT + tx*8+c], __float_as_uint(cmax[c]));
        atomicMin(&sredmin[LT + tx*8+c], __float_as_uint(cmin[c]));
    }
    __syncthreads();
    int row = (tid < LT) ? (iBase + tid) : (jBase + (tid - LT));
    atomicMax(&g_max2[row], sredmax[tid]);
    atomicMin(&g_min2[row], sredmin[tid]);
}

// ======================= legacy finalize (fallback path only) ===============
__global__ void partial_kernel(const int* __restrict__ tgt, int n) {
    __shared__ float ssum[256];
    int flag = g_flag;
    int chunk = (n + NPART - 1) / NPART;
    int beg = blockIdx.x * chunk;
    int end = min(beg + chunk, n);
    float s = 0.f;
    for (int i = beg + (int)threadIdx.x; i < end; i += blockDim.x) {
        float ap = sqrtf(__uint_as_float(g_max2[i]));
        float an = flag ? sqrtf(__uint_as_float(g_min2[i])) : 0.f;
        s += fmaxf(ap - an + MARGIN, 0.f);
    }
    ssum[threadIdx.x] = s;
    __syncthreads();
    #pragma unroll
    for (int o = 128; o; o >>= 1) {
        if (threadIdx.x < o) ssum[threadIdx.x] += ssum[threadIdx.x + o];
        __syncthreads();
    }
    if (threadIdx.x == 0) g_partial[blockIdx.x] = ssum[0];
}

__global__ void final_kernel(float* __restrict__ out, int n) {
    if (threadIdx.x == 0) {
        float s = 0.f;
        #pragma unroll
        for (int b = 0; b < NPART; b++) s += g_partial[b];
        out[0] = s / (float)n;
    }
}

// ======================= host launcher ======================================
extern "C" void kernel_launch(void* const* d_in, const int* in_sizes, int n_in,
                              void* d_out, int out_size) {
    const float* x   = (const float*)d_in[0];
    const int*   tgt = (const int*)d_in[1];   // int32 (JAX x64 disabled)
    int n = in_sizes[1];
    int d = in_sizes[0] / n;

    prep_kernel<<<(n + 7) / 8, 256>>>(x, tgt, n, d);

    bool tc_ok = (n % BNJ == 0) && (d % BK == 0) &&
                 ((size_t)n * d <= (size_t)N_MAX * D_MAX);
    if (tc_ok) {
        static bool attr_set = false;
        if (!attr_set) {
            cudaFuncSetAttribute(gemm_mma_kernel,
                                 cudaFuncAttributeMaxDynamicSharedMemorySize, SM_TOTAL);
            attr_set = true;
        }
        int nbj = n / BNJ;
        int nblocks = nbj * nbj + nbj;     // sum over bj of (2*bj + 2)
        gemm_mma_kernel<<<nblocks, 256, SM_TOTAL>>>(tgt, (float*)d_out, n, d, nbj);
    } else {
        int nb = n / LT;
        int nblocks = nb * (nb + 1) / 2;
        gemm_reduce_legacy<<<nblocks, 256>>>(x, tgt, n, d, nb);
        partial_kernel<<<NPART, 256>>>(tgt, n);
        final_kernel<<<1, 32>>>((float*)d_out, n);
    }
}

// round 9
// speedup vs baseline: 1.2512x; 1.2512x over previous
#include <cuda_runtime.h>
#include <cuda_bf16.h>
#include <cstdint>

#define N_MAX   4096
#define D_MAX   2048
#define MARGIN  0.3f
#define NPART   16

__device__ float           g_sq[N_MAX];
__device__ unsigned        g_max2[N_MAX];  // max clamped dist^2, same-class (uint-encoded fp32 >= 0)
__device__ unsigned        g_min2[N_MAX];  // min clamped dist^2, zero_neg   (uint-encoded fp32 >= 0)
__device__ int             g_flag;
__device__ int             g_done;
__device__ float           g_partial[NPART];
__device__ __nv_bfloat16   g_xb[(size_t)N_MAX * D_MAX];   // bf16 copy of inputs (16 MB)

// ======================= prep: norms (fp32 exact) + bf16 convert + flag =====
__global__ void prep_kernel(const float* __restrict__ x, const int* __restrict__ tgt,
                            int n, int d) {
    int warp = (blockIdx.x * blockDim.x + threadIdx.x) >> 5;
    int lane = threadIdx.x & 31;

    if (warp < n) {
        const float4* row = (const float4*)(x + (size_t)warp * d);
        uint4* orow = (uint4*)(g_xb + (size_t)warp * d);
        int nv = d >> 3;
        float s = 0.f;
        for (int v = lane; v < nv; v += 32) {
            float4 f0 = row[v * 2];
            float4 f1 = row[v * 2 + 1];
            s += f0.x * f0.x + f0.y * f0.y + f0.z * f0.z + f0.w * f0.w;
            s += f1.x * f1.x + f1.y * f1.y + f1.z * f1.z + f1.w * f1.w;
            __nv_bfloat162 h0 = __floats2bfloat162_rn(f0.x, f0.y);
            __nv_bfloat162 h1 = __floats2bfloat162_rn(f0.z, f0.w);
            __nv_bfloat162 h2 = __floats2bfloat162_rn(f1.x, f1.y);
            __nv_bfloat162 h3 = __floats2bfloat162_rn(f1.z, f1.w);
            uint4 o;
            o.x = *(uint32_t*)&h0; o.y = *(uint32_t*)&h1;
            o.z = *(uint32_t*)&h2; o.w = *(uint32_t*)&h3;
            orow[v] = o;
        }
        #pragma unroll
        for (int o = 16; o; o >>= 1) s += __shfl_xor_sync(0xffffffffu, s, o);
        if (lane == 0) {
            g_sq[warp]   = s;
            g_max2[warp] = 0u;
            g_min2[warp] = 0x7f800000u;
        }
    }

    if (blockIdx.x == 0) {
        int t0 = tgt[0];
        int loc = 0;
        for (int j = threadIdx.x; j < n; j += blockDim.x) {
            int tj = tgt[j];
            if ((t0 != tj) && (t0 == 0 || tj == 0)) loc = 1;
        }
        int f = __syncthreads_or(loc);
        if (threadIdx.x == 0) { g_flag = f; g_done = 0; }
    }
}

// ======================= PTX helpers (baseline ISA only) ====================
__device__ __forceinline__ uint32_t smem_u32(const void* p) {
    uint32_t a;
    asm("{ .reg .u64 t; cvta.to.shared.u64 t, %1; cvt.u32.u64 %0, t; }" : "=r"(a) : "l"(p));
    return a;
}
#define CP16(sa, ga) \
    asm volatile("cp.async.cg.shared.global [%0], [%1], 16;" :: "r"(sa), "l"(ga) : "memory")
#define CP_COMMIT()  asm volatile("cp.async.commit_group;" ::: "memory")
#define CP_WAIT1()   asm volatile("cp.async.wait_group 1;" ::: "memory")

#define LDSM_X4(r, a) \
    asm volatile("ldmatrix.sync.aligned.m8n8.x4.shared.b16 {%0,%1,%2,%3}, [%4];" \
        : "=r"((r)[0]), "=r"((r)[1]), "=r"((r)[2]), "=r"((r)[3]) : "r"(a))
#define LDSM_X2(r, a) \
    asm volatile("ldmatrix.sync.aligned.m8n8.x2.shared.b16 {%0,%1}, [%2];" \
        : "=r"((r)[0]), "=r"((r)[1]) : "r"(a))

#define MMA16816(c, a, b) \
    asm volatile("mma.sync.aligned.m16n8k16.row.col.f32.bf16.bf16.f32 " \
        "{%0,%1,%2,%3},{%4,%5,%6,%7},{%8,%9},{%0,%1,%2,%3};" \
        : "+f"((c)[0]), "+f"((c)[1]), "+f"((c)[2]), "+f"((c)[3]) \
        : "r"((a)[0]), "r"((a)[1]), "r"((a)[2]), "r"((a)[3]), "r"((b)[0]), "r"((b)[1]))

// ======================= bf16 mma.sync fused GEMM + reduction + loss ========
// Block tile 128x128, 8 warps in 2x4 grid (warp tile 64x32), K stage = 64.
#define BM    128
#define BKE   64                 // bf16 elems per K stage (128 B rows)
#define SROW  144                // smem row stride (bytes) -> conflict-free ldmatrix
#define STG_M (BM * SROW)        // 18432 per matrix per stage
#define STG   (2 * STG_M)        // 36864 per stage
#define NSTG  3
#define SM_RED   (NSTG * STG)              // 110592
#define SM_TOTAL (SM_RED + 2048)           // 112640

__global__ void __launch_bounds__(256, 2)
gemm_mma_kernel(const int* __restrict__ tgt, float* __restrict__ out,
                int n, int d, int nb) {
    extern __shared__ char smem[];
    const uint32_t smemu = smem_u32(smem);
    const int tid  = threadIdx.x;
    const int wid  = tid >> 5;
    const int lane = tid & 31;

    // triangular tile map (bi <= bj)
    int p = blockIdx.x, bi = 0, rem = p;
    while (rem >= nb - bi) { rem -= (nb - bi); bi++; }
    int bj = bi + rem;
    const int iBase = bi * BM;
    const int jBase = bj * BM;

    const __nv_bfloat16* xb = g_xb;
    const int nkt = d / BKE;     // 32 stages

    // warp tiling: 2 (M) x 4 (N) warps, warp tile 64x32
    const int mWarp = (wid >> 2) * 64;
    const int nWarp = (wid & 3) * 32;

    float acc[4][4][4];
    #pragma unroll
    for (int mt = 0; mt < 4; mt++)
        #pragma unroll
        for (int nt = 0; nt < 4; nt++)
            #pragma unroll
            for (int e = 0; e < 4; e++) acc[mt][nt][e] = 0.f;

    // per-thread cp.async bases: 128 rows x 8 chunks of 16B = 1024 tasks, 4/thread
    const char* baseA[4];
    const char* baseB[4];
    uint32_t    soff[4];
    #pragma unroll
    for (int t = 0; t < 4; t++) {
        int chunk = tid + t * 256;
        int r = chunk >> 3, c = chunk & 7;
        baseA[t] = (const char*)(xb + (size_t)(iBase + r) * d) + c * 16;
        baseB[t] = (const char*)(xb + (size_t)(jBase + r) * d) + c * 16;
        soff[t]  = r * SROW + c * 16;
    }

    auto issue = [&](int s, int kt) {
        uint32_t aS = smemu + s * STG;
        uint32_t bS = aS + STG_M;
        int koff = kt * 128;
        #pragma unroll
        for (int t = 0; t < 4; t++) {
            CP16(aS + soff[t], baseA[t] + koff);
            CP16(bS + soff[t], baseB[t] + koff);
        }
    };

    issue(0, 0); CP_COMMIT();
    issue(1, 1); CP_COMMIT();

    const uint32_t aRowOff = (mWarp + (lane & 15)) * SROW + ((lane >> 4) & 1) * 16;
    const uint32_t bRowOff = (nWarp + (lane & 7))  * SROW + ((lane >> 3) & 1) * 16;

    for (int kt = 0; kt < nkt; kt++) {
        CP_WAIT1();
        __syncthreads();
        if (kt + 2 < nkt) { issue((kt + 2) % NSTG, kt + 2); }
        CP_COMMIT();

        int s = kt % NSTG;
        uint32_t aS = smemu + s * STG;
        uint32_t bS = aS + STG_M;
        #pragma unroll
        for (int kk = 0; kk < 4; kk++) {
            uint32_t rb[4][2];
            #pragma unroll
            for (int nt = 0; nt < 4; nt++)
                LDSM_X2(rb[nt], bS + bRowOff + nt * 8 * SROW + kk * 32);
            #pragma unroll
            for (int mt = 0; mt < 4; mt++) {
                uint32_t ra[4];
                LDSM_X4(ra, aS + aRowOff + mt * 16 * SROW + kk * 32);
                #pragma unroll
                for (int nt = 0; nt < 4; nt++)
                    MMA16816(acc[mt][nt], ra, rb[nt]);
            }
        }
    }
    __syncthreads();

    // --- epilogue: dist^2 + masked max/min reductions ------------------------
    // acc fragment (m16n8): e0:(r,c) e1:(r,c+1) e2:(r+8,c) e3:(r+8,c+1)
    float sqi[8], sqj[8];
    int   ti[8], tj[8];
    #pragma unroll
    for (int mt = 0; mt < 4; mt++)
        #pragma unroll
        for (int h = 0; h < 2; h++) {
            int gi = iBase + mWarp + mt * 16 + (lane >> 2) + h * 8;
            sqi[mt * 2 + h] = g_sq[gi];
            ti[mt * 2 + h]  = tgt[gi];
        }
    #pragma unroll
    for (int nt = 0; nt < 4; nt++)
        #pragma unroll
        for (int pp = 0; pp < 2; pp++) {
            int gj = jBase + nWarp + nt * 8 + 2 * (lane & 3) + pp;
            sqj[nt * 2 + pp] = g_sq[gj];
            tj[nt * 2 + pp]  = tgt[gj];
        }

    const unsigned UINF = 0x7f800000u;
    unsigned rmax[8], rmin[8], cmax[8], cmin[8];
    #pragma unroll
    for (int q = 0; q < 8; q++) { rmax[q] = 0u; rmin[q] = UINF; cmax[q] = 0u; cmin[q] = UINF; }

    #pragma unroll
    for (int mt = 0; mt < 4; mt++)
        #pragma unroll
        for (int nt = 0; nt < 4; nt++)
            #pragma unroll
            for (int e = 0; e < 4; e++) {
                int h = e >> 1, pp = e & 1;
                int ri = mt * 2 + h, cj = nt * 2 + pp;
                float d2 = fmaxf(sqi[ri] + sqj[cj] - 2.f * acc[mt][nt][(h << 1) | pp], 1e-12f);
                unsigned b = __float_as_uint(d2);
                bool same = (ti[ri] == tj[cj]);
                bool zn   = !same && (ti[ri] == 0 || tj[cj] == 0);
                if (same) { rmax[ri] = max(rmax[ri], b); cmax[cj] = max(cmax[cj], b); }
                if (zn)   { rmin[ri] = min(rmin[ri], b); cmin[cj] = min(cmin[cj], b); }
            }

    unsigned* sredmax = (unsigned*)(smem + SM_RED);
    unsigned* sredmin = sredmax + 256;
    sredmax[tid] = 0u;
    sredmin[tid] = UINF;
    __syncthreads();

    #pragma unroll
    for (int mt = 0; mt < 4; mt++)
        #pragma unroll
        for (int h = 0; h < 2; h++) {
            int q = mt * 2 + h;
            int loc = mWarp + mt * 16 + (lane >> 2) + h * 8;
            if (rmax[q]) atomicMax(&sredmax[loc], rmax[q]);
            if (rmin[q] != UINF) atomicMin(&sredmin[loc], rmin[q]);
        }
    #pragma unroll
    for (int nt = 0; nt < 4; nt++)
        #pragma unroll
        for (int pp = 0; pp < 2; pp++) {
            int q = nt * 2 + pp;
            int loc = 128 + nWarp + nt * 8 + 2 * (lane & 3) + pp;
            if (cmax[q]) atomicMax(&sredmax[loc], cmax[q]);
            if (cmin[q] != UINF) atomicMin(&sredmin[loc], cmin[q]);
        }
    __syncthreads();

    int row = (tid < 128) ? (iBase + tid) : (jBase + (tid - 128));
    if (sredmax[tid]) atomicMax(&g_max2[row], sredmax[tid]);
    if (sredmin[tid] != UINF) atomicMin(&g_min2[row], sredmin[tid]);

    // --- last-CTA tail: full loss reduction ----------------------------------
    __threadfence();
    __shared__ int amlast;
    if (tid == 0) amlast = (atomicAdd(&g_done, 1) == (int)gridDim.x - 1);
    __syncthreads();
    if (amlast) {
        int flag = g_flag;
        float s = 0.f;
        for (int i = tid; i < n; i += 256) {
            float ap = sqrtf(__uint_as_float(__ldcg(&g_max2[i])));
            float an = flag ? sqrtf(__uint_as_float(__ldcg(&g_min2[i]))) : 0.f;
            s += fmaxf(ap - an + MARGIN, 0.f);   // min2==+inf & flag -> -inf -> 0
        }
        float* ssum = (float*)(smem + SM_RED);
        ssum[tid] = s;
        __syncthreads();
        #pragma unroll
        for (int o = 128; o; o >>= 1) {
            if (tid < o) ssum[tid] += ssum[tid + o];
            __syncthreads();
        }
        if (tid == 0) out[0] = ssum[0] / (float)n;
    }
}

// ======================= legacy fp32 fallback (proven) ======================
#define LT    128
#define LKT   16
#define LPAD  4
__global__ void __launch_bounds__(256, 2)
gemm_reduce_legacy(const float* __restrict__ x, const int* __restrict__ tgt,
                   int n, int d, int nb) {
    int p = blockIdx.x, bi = 0, rem = p;
    while (rem >= nb - bi) { rem -= (nb - bi); bi++; }
    int bj = bi + rem;
    const int iBase = bi * LT;
    const int jBase = bj * LT;
    const int tid = threadIdx.x;
    const int tx = tid & 15;
    const int ty = tid >> 4;

    __shared__ float As[LKT][LT + LPAD];
    __shared__ float Bs[LKT][LT + LPAD];
    __shared__ unsigned sredmax[2 * LT];
    __shared__ unsigned sredmin[2 * LT];

    float acc[8][8];
    #pragma unroll
    for (int r = 0; r < 8; r++)
        #pragma unroll
        for (int c = 0; c < 8; c++) acc[r][c] = 0.f;

    const int nkt = d / LKT;
    float4 pa[2], pb[2];
    #pragma unroll
    for (int u = 0; u < 2; u++) {
        int idx = tid + u * 256, r = idx >> 2, c4 = idx & 3;
        pa[u] = *(const float4*)(x + (size_t)(iBase + r) * d + c4 * 4);
        pb[u] = *(const float4*)(x + (size_t)(jBase + r) * d + c4 * 4);
    }
    #pragma unroll
    for (int u = 0; u < 2; u++) {
        int idx = tid + u * 256, r = idx >> 2, c4 = idx & 3;
        As[c4*4+0][r]=pa[u].x; As[c4*4+1][r]=pa[u].y; As[c4*4+2][r]=pa[u].z; As[c4*4+3][r]=pa[u].w;
        Bs[c4*4+0][r]=pb[u].x; Bs[c4*4+1][r]=pb[u].y; Bs[c4*4+2][r]=pb[u].z; Bs[c4*4+3][r]=pb[u].w;
    }
    __syncthreads();
    for (int kt = 0; kt < nkt; kt++) {
        if (kt + 1 < nkt) {
            int k0 = (kt + 1) * LKT;
            #pragma unroll
            for (int u = 0; u < 2; u++) {
                int idx = tid + u * 256, r = idx >> 2, c4 = idx & 3;
                pa[u] = *(const float4*)(x + (size_t)(iBase + r) * d + k0 + c4 * 4);
                pb[u] = *(const float4*)(x + (size_t)(jBase + r) * d + k0 + c4 * 4);
            }
        }
        #pragma unroll
        for (int k = 0; k < LKT; k++) {
            float a[8], b[8];
            *(float4*)(a)   = *(const float4*)&As[k][ty*8];
            *(float4*)(a+4) = *(const float4*)&As[k][ty*8+4];
            *(float4*)(b)   = *(const float4*)&Bs[k][tx*8];
            *(float4*)(b+4) = *(const float4*)&Bs[k][tx*8+4];
            #pragma unroll
            for (int r = 0; r < 8; r++)
                #pragma unroll
                for (int c = 0; c < 8; c++) acc[r][c] += a[r] * b[c];
        }
        __syncthreads();
        if (kt + 1 < nkt) {
            #pragma unroll
            for (int u = 0; u < 2; u++) {
                int idx = tid + u * 256, r = idx >> 2, c4 = idx & 3;
                As[c4*4+0][r]=pa[u].x; As[c4*4+1][r]=pa[u].y; As[c4*4+2][r]=pa[u].z; As[c4*4+3][r]=pa[u].w;
                Bs[c4*4+0][r]=pb[u].x; Bs[c4*4+1][r]=pb[u].y; Bs[c4*4+2][r]=pb[u].z; Bs[c4*4+3][r]=pb[u].w;
            }
            __syncthreads();
        }
    }

    float sqi[8], sqj[8];
    int ti8[8], tj8[8];
    #pragma unroll
    for (int r = 0; r < 8; r++) { int i = iBase + ty*8 + r; sqi[r] = g_sq[i]; ti8[r] = tgt[i]; }
    #pragma unroll
    for (int c = 0; c < 8; c++) { int j = jBase + tx*8 + c; sqj[c] = g_sq[j]; tj8[c] = tgt[j]; }

    const float INF = __uint_as_float(0x7f800000u);
    float rmax[8], rmin[8], cmax[8], cmin[8];
    #pragma unroll
    for (int r = 0; r < 8; r++) { rmax[r] = 0.f; rmin[r] = INF; }
    #pragma unroll
    for (int c = 0; c < 8; c++) { cmax[c] = 0.f; cmin[c] = INF; }
    #pragma unroll
    for (int r = 0; r < 8; r++)
        #pragma unroll
        for (int c = 0; c < 8; c++) {
            float d2 = fmaxf(sqi[r] + sqj[c] - 2.f * acc[r][c], 1e-12f);
            bool same = (ti8[r] == tj8[c]);
            bool zn = !same && (ti8[r] == 0 || tj8[c] == 0);
            if (same) { rmax[r] = fmaxf(rmax[r], d2); cmax[c] = fmaxf(cmax[c], d2); }
            if (zn)   { rmin[r] = fminf(rmin[r], d2); cmin[c] = fminf(cmin[c], d2); }
        }
    sredmax[tid] = 0u; sredmin[tid] = 0x7f800000u;
    __syncthreads();
    #pragma unroll
    for (int r = 0; r < 8; r++) {
        atomicMax(&sredmax[ty*8+r], __float_as_uint(rmax[r]));
        atomicMin(&sredmin[ty*8+r], __float_as_uint(rmin[r]));
    }
    #pragma unroll
    for (int c = 0; c < 8; c++) {
        atomicMax(&sredmax[LT + tx*8+c], __float_as_uint(cmax[c]));
        atomicMin(&sredmin[LT + tx*8+c], __float_as_uint(cmin[c]));
    }
    __syncthreads();
    int row = (tid < LT) ? (iBase + tid) : (jBase + (tid - LT));
    atomicMax(&g_max2[row], sredmax[tid]);
    atomicMin(&g_min2[row], sredmin[tid]);
}

// ======================= legacy finalize (fallback path only) ===============
__global__ void partial_kernel(const int* __restrict__ tgt, int n) {
    __shared__ float ssum[256];
    int flag = g_flag;
    int chunk = (n + NPART - 1) / NPART;
    int beg = blockIdx.x * chunk;
    int end = min(beg + chunk, n);
    float s = 0.f;
    for (int i = beg + (int)threadIdx.x; i < end; i += blockDim.x) {
        float ap = sqrtf(__uint_as_float(g_max2[i]));
        float an = flag ? sqrtf(__uint_as_float(g_min2[i])) : 0.f;
        s += fmaxf(ap - an + MARGIN, 0.f);
    }
    ssum[threadIdx.x] = s;
    __syncthreads();
    #pragma unroll
    for (int o = 128; o; o >>= 1) {
        if (threadIdx.x < o) ssum[threadIdx.x] += ssum[threadIdx.x + o];
        __syncthreads();
    }
    if (threadIdx.x == 0) g_partial[blockIdx.x] = ssum[0];
}

__global__ void final_kernel(float* __restrict__ out, int n) {
    if (threadIdx.x == 0) {
        float s = 0.f;
        #pragma unroll
        for (int b = 0; b < NPART; b++) s += g_partial[b];
        out[0] = s / (float)n;
    }
}

// ======================= host launcher ======================================
extern "C" void kernel_launch(void* const* d_in, const int* in_sizes, int n_in,
                              void* d_out, int out_size) {
    const float* x   = (const float*)d_in[0];
    const int*   tgt = (const int*)d_in[1];   // int32 (JAX x64 disabled)
    int n = in_sizes[1];
    int d = in_sizes[0] / n;

    prep_kernel<<<(n + 7) / 8, 256>>>(x, tgt, n, d);

    bool tc_ok = (n % BM == 0) && (d % BKE == 0) && (d / BKE >= 2) &&
                 ((size_t)n * d <= (size_t)N_MAX * D_MAX);
    if (tc_ok) {
        static bool attr_set = false;
        if (!attr_set) {
            cudaFuncSetAttribute(gemm_mma_kernel,
                                 cudaFuncAttributeMaxDynamicSharedMemorySize, SM_TOTAL);
            attr_set = true;
        }
        int nb = n / BM;
        int nblocks = nb * (nb + 1) / 2;
        gemm_mma_kernel<<<nblocks, 256, SM_TOTAL>>>(tgt, (float*)d_out, n, d, nb);
    } else {
        int nb = n / LT;
        int nblocks = nb * (nb + 1) / 2;
        gemm_reduce_legacy<<<nblocks, 256>>>(x, tgt, n, d, nb);
        partial_kernel<<<NPART, 256>>>(tgt, n);
        final_kernel<<<1, 32>>>((float*)d_out, n);
    }
}

// round 10
// speedup vs baseline: 1.2515x; 1.0002x over previous
#include <cuda_runtime.h>
#include <cuda_bf16.h>
#include <cstdint>

#define N_MAX   4096
#define D_MAX   2048
#define MARGIN  0.3f
#define NPART   16

__device__ float           g_sq[N_MAX];
__device__ unsigned        g_max2[N_MAX];  // max clamped dist^2, same-class (uint-encoded fp32 >= 0)
__device__ unsigned        g_min2[N_MAX];  // min clamped dist^2, zero_neg   (uint-encoded fp32 >= 0)
__device__ int             g_flag;
__device__ int             g_done;
__device__ float           g_partial[NPART];
__device__ __nv_bfloat16   g_xb[(size_t)N_MAX * D_MAX];   // bf16 copy of inputs (16 MB)

// ======================= prep: norms (fp32 exact) + bf16 convert + flag =====
__global__ void prep_kernel(const float* __restrict__ x, const int* __restrict__ tgt,
                            int n, int d) {
    int warp = (blockIdx.x * blockDim.x + threadIdx.x) >> 5;
    int lane = threadIdx.x & 31;

    if (warp < n) {
        const float4* row = (const float4*)(x + (size_t)warp * d);
        uint4* orow = (uint4*)(g_xb + (size_t)warp * d);
        int nv = d >> 3;
        float s = 0.f;
        for (int v = lane; v < nv; v += 32) {
            float4 f0 = row[v * 2];
            float4 f1 = row[v * 2 + 1];
            s += f0.x * f0.x + f0.y * f0.y + f0.z * f0.z + f0.w * f0.w;
            s += f1.x * f1.x + f1.y * f1.y + f1.z * f1.z + f1.w * f1.w;
            __nv_bfloat162 h0 = __floats2bfloat162_rn(f0.x, f0.y);
            __nv_bfloat162 h1 = __floats2bfloat162_rn(f0.z, f0.w);
            __nv_bfloat162 h2 = __floats2bfloat162_rn(f1.x, f1.y);
            __nv_bfloat162 h3 = __floats2bfloat162_rn(f1.z, f1.w);
            uint4 o;
            o.x = *(uint32_t*)&h0; o.y = *(uint32_t*)&h1;
            o.z = *(uint32_t*)&h2; o.w = *(uint32_t*)&h3;
            orow[v] = o;
        }
        #pragma unroll
        for (int o = 16; o; o >>= 1) s += __shfl_xor_sync(0xffffffffu, s, o);
        if (lane == 0) {
            g_sq[warp]   = s;
            g_max2[warp] = 0u;
            g_min2[warp] = 0x7f800000u;
        }
    }

    if (blockIdx.x == 0) {
        int t0 = tgt[0];
        int loc = 0;
        for (int j = threadIdx.x; j < n; j += blockDim.x) {
            int tj = tgt[j];
            if ((t0 != tj) && (t0 == 0 || tj == 0)) loc = 1;
        }
        int f = __syncthreads_or(loc);
        if (threadIdx.x == 0) { g_flag = f; g_done = 0; }
    }
}

// ======================= PTX helpers (baseline ISA only) ====================
__device__ __forceinline__ uint32_t smem_u32(const void* p) {
    uint32_t a;
    asm("{ .reg .u64 t; cvta.to.shared.u64 t, %1; cvt.u32.u64 %0, t; }" : "=r"(a) : "l"(p));
    return a;
}
#define CP16(sa, ga) \
    asm volatile("cp.async.cg.shared.global [%0], [%1], 16;" :: "r"(sa), "l"(ga) : "memory")
#define CP_COMMIT()  asm volatile("cp.async.commit_group;" ::: "memory")
#define CP_WAIT1()   asm volatile("cp.async.wait_group 1;" ::: "memory")

#define LDSM_X4(r, a) \
    asm volatile("ldmatrix.sync.aligned.m8n8.x4.shared.b16 {%0,%1,%2,%3}, [%4];" \
        : "=r"((r)[0]), "=r"((r)[1]), "=r"((r)[2]), "=r"((r)[3]) : "r"(a))
#define LDSM_X2(r, a) \
    asm volatile("ldmatrix.sync.aligned.m8n8.x2.shared.b16 {%0,%1}, [%2];" \
        : "=r"((r)[0]), "=r"((r)[1]) : "r"(a))

#define MMA16816(c, a, b) \
    asm volatile("mma.sync.aligned.m16n8k16.row.col.f32.bf16.bf16.f32 " \
        "{%0,%1,%2,%3},{%4,%5,%6,%7},{%8,%9},{%0,%1,%2,%3};" \
        : "+f"((c)[0]), "+f"((c)[1]), "+f"((c)[2]), "+f"((c)[3]) \
        : "r"((a)[0]), "r"((a)[1]), "r"((a)[2]), "r"((a)[3]), "r"((b)[0]), "r"((b)[1]))

// ======================= bf16 mma.sync fused GEMM + reduction + loss ========
// Block tile 128x128, 8 warps in 2x4 grid (warp tile 64x32), K stage = 64.
#define BM    128
#define BKE   64                 // bf16 elems per K stage (128 B rows)
#define SROW  144                // smem row stride (bytes) -> conflict-free ldmatrix
#define STG_M (BM * SROW)        // 18432 per matrix per stage
#define STG   (2 * STG_M)        // 36864 per stage
#define NSTG  3
#define SM_RED   (NSTG * STG)              // 110592
#define SM_TOTAL (SM_RED + 2048)           // 112640

__global__ void __launch_bounds__(256, 2)
gemm_mma_kernel(const int* __restrict__ tgt, float* __restrict__ out,
                int n, int d, int nb) {
    extern __shared__ char smem[];
    const uint32_t smemu = smem_u32(smem);
    const int tid  = threadIdx.x;
    const int wid  = tid >> 5;
    const int lane = tid & 31;

    // triangular tile map (bi <= bj)
    int p = blockIdx.x, bi = 0, rem = p;
    while (rem >= nb - bi) { rem -= (nb - bi); bi++; }
    int bj = bi + rem;
    const int iBase = bi * BM;
    const int jBase = bj * BM;

    const int nkt = d / BKE;     // 32 stages
    const size_t dB = (size_t)d * 2;              // row stride in bytes
    const char* pA = (const char*)(g_xb) + (size_t)iBase * dB;
    const char* pB = (const char*)(g_xb) + (size_t)jBase * dB;

    // warp tiling: 2 (M) x 4 (N) warps, warp tile 64x32
    const int mWarp = (wid >> 2) * 64;
    const int nWarp = (wid & 3) * 32;

    float acc[4][4][4];
    #pragma unroll
    for (int mt = 0; mt < 4; mt++)
        #pragma unroll
        for (int nt = 0; nt < 4; nt++)
            #pragma unroll
            for (int e = 0; e < 4; e++) acc[mt][nt][e] = 0.f;

    // cp.async: 128 rows x 8 chunks of 16B per matrix = 1024 tasks, 4/thread.
    // Addresses recomputed per issue (rematerializable -> low reg pressure).
    auto issue = [&](int s, int kt) {
        uint32_t aS = smemu + s * STG;
        uint32_t bS = aS + STG_M;
        int koff = kt * 128;
        #pragma unroll
        for (int t = 0; t < 4; t++) {
            int chunk = tid + t * 256;
            int r = chunk >> 3;
            int c = (chunk & 7) * 16;
            uint32_t so = r * SROW + c;
            size_t go = (size_t)r * dB + koff + c;
            CP16(aS + so, pA + go);
            CP16(bS + so, pB + go);
        }
    };

    issue(0, 0); CP_COMMIT();
    issue(1, 1); CP_COMMIT();

    const uint32_t aRowOff = (mWarp + (lane & 15)) * SROW + ((lane >> 4) & 1) * 16;
    const uint32_t bRowOff = (nWarp + (lane & 7))  * SROW + ((lane >> 3) & 1) * 16;

    for (int kt = 0; kt < nkt; kt++) {
        CP_WAIT1();
        __syncthreads();
        if (kt + 2 < nkt) { issue((kt + 2) % NSTG, kt + 2); }
        CP_COMMIT();

        int s = kt % NSTG;
        uint32_t aS = smemu + s * STG;
        uint32_t bS = aS + STG_M;

        // B fragments double-buffered across kk; A fragments hoisted per kk.
        uint32_t rb[2][4][2];
        #pragma unroll
        for (int nt = 0; nt < 4; nt++)
            LDSM_X2(rb[0][nt], bS + bRowOff + nt * 8 * SROW);

        #pragma unroll
        for (int kk = 0; kk < 4; kk++) {
            uint32_t ra[4][4];
            #pragma unroll
            for (int mt = 0; mt < 4; mt++)
                LDSM_X4(ra[mt], aS + aRowOff + mt * 16 * SROW + kk * 32);
            if (kk < 3) {
                #pragma unroll
                for (int nt = 0; nt < 4; nt++)
                    LDSM_X2(rb[(kk + 1) & 1][nt],
                            bS + bRowOff + nt * 8 * SROW + (kk + 1) * 32);
            }
            #pragma unroll
            for (int mt = 0; mt < 4; mt++)
                #pragma unroll
                for (int nt = 0; nt < 4; nt++)
                    MMA16816(acc[mt][nt], ra[mt], rb[kk & 1][nt]);
        }
    }
    __syncthreads();

    // --- epilogue: dist^2 + masked max/min reductions ------------------------
    // acc fragment (m16n8): e0:(r,c) e1:(r,c+1) e2:(r+8,c) e3:(r+8,c+1)
    float sqi[8], sqj[8];
    int   ti[8], tj[8];
    #pragma unroll
    for (int mt = 0; mt < 4; mt++)
        #pragma unroll
        for (int h = 0; h < 2; h++) {
            int gi = iBase + mWarp + mt * 16 + (lane >> 2) + h * 8;
            sqi[mt * 2 + h] = g_sq[gi];
            ti[mt * 2 + h]  = tgt[gi];
        }
    #pragma unroll
    for (int nt = 0; nt < 4; nt++)
        #pragma unroll
        for (int pp = 0; pp < 2; pp++) {
            int gj = jBase + nWarp + nt * 8 + 2 * (lane & 3) + pp;
            sqj[nt * 2 + pp] = g_sq[gj];
            tj[nt * 2 + pp]  = tgt[gj];
        }

    const unsigned UINF = 0x7f800000u;
    unsigned rmax[8], rmin[8], cmax[8], cmin[8];
    #pragma unroll
    for (int q = 0; q < 8; q++) { rmax[q] = 0u; rmin[q] = UINF; cmax[q] = 0u; cmin[q] = UINF; }

    #pragma unroll
    for (int mt = 0; mt < 4; mt++)
        #pragma unroll
        for (int nt = 0; nt < 4; nt++)
            #pragma unroll
            for (int e = 0; e < 4; e++) {
                int h = e >> 1, pp = e & 1;
                int ri = mt * 2 + h, cj = nt * 2 + pp;
                float d2 = fmaxf(sqi[ri] + sqj[cj] - 2.f * acc[mt][nt][(h << 1) | pp], 1e-12f);
                unsigned b = __float_as_uint(d2);
                bool same = (ti[ri] == tj[cj]);
                bool zn   = !same && (ti[ri] == 0 || tj[cj] == 0);
                if (same) { rmax[ri] = max(rmax[ri], b); cmax[cj] = max(cmax[cj], b); }
                if (zn)   { rmin[ri] = min(rmin[ri], b); cmin[cj] = min(cmin[cj], b); }
            }

    unsigned* sredmax = (unsigned*)(smem + SM_RED);
    unsigned* sredmin = sredmax + 256;
    sredmax[tid] = 0u;
    sredmin[tid] = UINF;
    __syncthreads();

    #pragma unroll
    for (int mt = 0; mt < 4; mt++)
        #pragma unroll
        for (int h = 0; h < 2; h++) {
            int q = mt * 2 + h;
            int loc = mWarp + mt * 16 + (lane >> 2) + h * 8;
            if (rmax[q]) atomicMax(&sredmax[loc], rmax[q]);
            if (rmin[q] != UINF) atomicMin(&sredmin[loc], rmin[q]);
        }
    #pragma unroll
    for (int nt = 0; nt < 4; nt++)
        #pragma unroll
        for (int pp = 0; pp < 2; pp++) {
            int q = nt * 2 + pp;
            int loc = 128 + nWarp + nt * 8 + 2 * (lane & 3) + pp;
            if (cmax[q]) atomicMax(&sredmax[loc], cmax[q]);
            if (cmin[q] != UINF) atomicMin(&sredmin[loc], cmin[q]);
        }
    __syncthreads();

    int row = (tid < 128) ? (iBase + tid) : (jBase + (tid - 128));
    if (sredmax[tid]) atomicMax(&g_max2[row], sredmax[tid]);
    if (sredmin[tid] != UINF) atomicMin(&g_min2[row], sredmin[tid]);

    // --- last-CTA tail: full loss reduction ----------------------------------
    __threadfence();
    __shared__ int amlast;
    if (tid == 0) amlast = (atomicAdd(&g_done, 1) == (int)gridDim.x - 1);
    __syncthreads();
    if (amlast) {
        int flag = g_flag;
        float s = 0.f;
        for (int i = tid; i < n; i += 256) {
            float ap = sqrtf(__uint_as_float(__ldcg(&g_max2[i])));
            float an = flag ? sqrtf(__uint_as_float(__ldcg(&g_min2[i]))) : 0.f;
            s += fmaxf(ap - an + MARGIN, 0.f);   // min2==+inf & flag -> -inf -> 0
        }
        float* ssum = (float*)(smem + SM_RED);
        ssum[tid] = s;
        __syncthreads();
        #pragma unroll
        for (int o = 128; o; o >>= 1) {
            if (tid < o) ssum[tid] += ssum[tid + o];
            __syncthreads();
        }
        if (tid == 0) out[0] = ssum[0] / (float)n;
    }
}

// ======================= legacy fp32 fallback (proven) ======================
#define LT    128
#define LKT   16
#define LPAD  4
__global__ void __launch_bounds__(256, 2)
gemm_reduce_legacy(const float* __restrict__ x, const int* __restrict__ tgt,
                   int n, int d, int nb) {
    int p = blockIdx.x, bi = 0, rem = p;
    while (rem >= nb - bi) { rem -= (nb - bi); bi++; }
    int bj = bi + rem;
    const int iBase = bi * LT;
    const int jBase = bj * LT;
    const int tid = threadIdx.x;
    const int tx = tid & 15;
    const int ty = tid >> 4;

    __shared__ float As[LKT][LT + LPAD];
    __shared__ float Bs[LKT][LT + LPAD];
    __shared__ unsigned sredmax[2 * LT];
    __shared__ unsigned sredmin[2 * LT];

    float acc[8][8];
    #pragma unroll
    for (int r = 0; r < 8; r++)
        #pragma unroll
        for (int c = 0; c < 8; c++) acc[r][c] = 0.f;

    const int nkt = d / LKT;
    float4 pa[2], pb[2];
    #pragma unroll
    for (int u = 0; u < 2; u++) {
        int idx = tid + u * 256, r = idx >> 2, c4 = idx & 3;
        pa[u] = *(const float4*)(x + (size_t)(iBase + r) * d + c4 * 4);
        pb[u] = *(const float4*)(x + (size_t)(jBase + r) * d + c4 * 4);
    }
    #pragma unroll
    for (int u = 0; u < 2; u++) {
        int idx = tid + u * 256, r = idx >> 2, c4 = idx & 3;
        As[c4*4+0][r]=pa[u].x; As[c4*4+1][r]=pa[u].y; As[c4*4+2][r]=pa[u].z; As[c4*4+3][r]=pa[u].w;
        Bs[c4*4+0][r]=pb[u].x; Bs[c4*4+1][r]=pb[u].y; Bs[c4*4+2][r]=pb[u].z; Bs[c4*4+3][r]=pb[u].w;
    }
    __syncthreads();
    for (int kt = 0; kt < nkt; kt++) {
        if (kt + 1 < nkt) {
            int k0 = (kt + 1) * LKT;
            #pragma unroll
            for (int u = 0; u < 2; u++) {
                int idx = tid + u * 256, r = idx >> 2, c4 = idx & 3;
                pa[u] = *(const float4*)(x + (size_t)(iBase + r) * d + k0 + c4 * 4);
                pb[u] = *(const float4*)(x + (size_t)(jBase + r) * d + k0 + c4 * 4);
            }
        }
        #pragma unroll
        for (int k = 0; k < LKT; k++) {
            float a[8], b[8];
            *(float4*)(a)   = *(const float4*)&As[k][ty*8];
            *(float4*)(a+4) = *(const float4*)&As[k][ty*8+4];
            *(float4*)(b)   = *(const float4*)&Bs[k][tx*8];
            *(float4*)(b+4) = *(const float4*)&Bs[k][tx*8+4];
            #pragma unroll
            for (int r = 0; r < 8; r++)
                #pragma unroll
                for (int c = 0; c < 8; c++) acc[r][c] += a[r] * b[c];
        }
        __syncthreads();
        if (kt + 1 < nkt) {
            #pragma unroll
            for (int u = 0; u < 2; u++) {
                int idx = tid + u * 256, r = idx >> 2, c4 = idx & 3;
                As[c4*4+0][r]=pa[u].x; As[c4*4+1][r]=pa[u].y; As[c4*4+2][r]=pa[u].z; As[c4*4+3][r]=pa[u].w;
                Bs[c4*4+0][r]=pb[u].x; Bs[c4*4+1][r]=pb[u].y; Bs[c4*4+2][r]=pb[u].z; Bs[c4*4+3][r]=pb[u].w;
            }
            __syncthreads();
        }
    }

    float sqi[8], sqj[8];
    int ti8[8], tj8[8];
    #pragma unroll
    for (int r = 0; r < 8; r++) { int i = iBase + ty*8 + r; sqi[r] = g_sq[i]; ti8[r] = tgt[i]; }
    #pragma unroll
    for (int c = 0; c < 8; c++) { int j = jBase + tx*8 + c; sqj[c] = g_sq[j]; tj8[c] = tgt[j]; }

    const float INF = __uint_as_float(0x7f800000u);
    float rmax[8], rmin[8], cmax[8], cmin[8];
    #pragma unroll
    for (int r = 0; r < 8; r++) { rmax[r] = 0.f; rmin[r] = INF; }
    #pragma unroll
    for (int c = 0; c < 8; c++) { cmax[c] = 0.f; cmin[c] = INF; }
    #pragma unroll
    for (int r = 0; r < 8; r++)
        #pragma unroll
        for (int c = 0; c < 8; c++) {
            float d2 = fmaxf(sqi[r] + sqj[c] - 2.f * acc[r][c], 1e-12f);
            bool same = (ti8[r] == tj8[c]);
            bool zn = !same && (ti8[r] == 0 || tj8[c] == 0);
            if (same) { rmax[r] = fmaxf(rmax[r], d2); cmax[c] = fmaxf(cmax[c], d2); }
            if (zn)   { rmin[r] = fminf(rmin[r], d2); cmin[c] = fminf(cmin[c], d2); }
        }
    sredmax[tid] = 0u; sredmin[tid] = 0x7f800000u;
    __syncthreads();
    #pragma unroll
    for (int r = 0; r < 8; r++) {
        atomicMax(&sredmax[ty*8+r], __float_as_uint(rmax[r]));
        atomicMin(&sredmin[ty*8+r], __float_as_uint(rmin[r]));
    }
    #pragma unroll
    for (int c = 0; c < 8; c++) {
        atomicMax(&sredmax[LT + tx*8+c], __float_as_uint(cmax[c]));
        atomicMin(&sredmin[LT + tx*8+c], __float_as_uint(cmin[c]));
    }
    __syncthreads();
    int row = (tid < LT) ? (iBase + tid) : (jBase + (tid - LT));
    atomicMax(&g_max2[row], sredmax[tid]);
    atomicMin(&g_min2[row], sredmin[tid]);
}

// ======================= legacy finalize (fallback path only) ===============
__global__ void partial_kernel(const int* __restrict__ tgt, int n) {
    __shared__ float ssum[256];
    int flag = g_flag;
    int chunk = (n + NPART - 1) / NPART;
    int beg = blockIdx.x * chunk;
    int end = min(beg + chunk, n);
    float s = 0.f;
    for (int i = beg + (int)threadIdx.x; i < end; i += blockDim.x) {
        float ap = sqrtf(__uint_as_float(g_max2[i]));
        float an = flag ? sqrtf(__uint_as_float(g_min2[i])) : 0.f;
        s += fmaxf(ap - an + MARGIN, 0.f);
    }
    ssum[threadIdx.x] = s;
    __syncthreads();
    #pragma unroll
    for (int o = 128; o; o >>= 1) {
        if (threadIdx.x < o) ssum[threadIdx.x] += ssum[threadIdx.x + o];
        __syncthreads();
    }
    if (threadIdx.x == 0) g_partial[blockIdx.x] = ssum[0];
}

__global__ void final_kernel(float* __restrict__ out, int n) {
    if (threadIdx.x == 0) {
        float s = 0.f;
        #pragma unroll
        for (int b = 0; b < NPART; b++) s += g_partial[b];
        out[0] = s / (float)n;
    }
}

// ======================= host launcher ======================================
extern "C" void kernel_launch(void* const* d_in, const int* in_sizes, int n_in,
                              void* d_out, int out_size) {
    const float* x   = (const float*)d_in[0];
    const int*   tgt = (const int*)d_in[1];   // int32 (JAX x64 disabled)
    int n = in_sizes[1];
    int d = in_sizes[0] / n;

    prep_kernel<<<(n + 7) / 8, 256>>>(x, tgt, n, d);

    bool tc_ok = (n % BM == 0) && (d % BKE == 0) && (d / BKE >= 2) &&
                 ((size_t)n * d <= (size_t)N_MAX * D_MAX);
    if (tc_ok) {
        static bool attr_set = false;
        if (!attr_set) {
            cudaFuncSetAttribute(gemm_mma_kernel,
                                 cudaFuncAttributeMaxDynamicSharedMemorySize, SM_TOTAL);
            attr_set = true;
        }
        int nb = n / BM;
        int nblocks = nb * (nb + 1) / 2;
        gemm_mma_kernel<<<nblocks, 256, SM_TOTAL>>>(tgt, (float*)d_out, n, d, nb);
    } else {
        int nb = n / LT;
        int nblocks = nb * (nb + 1) / 2;
        gemm_reduce_legacy<<<nblocks, 256>>>(x, tgt, n, d, nb);
        partial_kernel<<<NPART, 256>>>(tgt, n);
        final_kernel<<<1, 32>>>((float*)d_out, n);
    }
}